// round 1
// baseline (speedup 1.0000x reference)
#include <cuda_runtime.h>
#include <math.h>

// ---------------- problem constants ----------------
#define BNODES   4096      // B*N
#define HDIM     256
#define NET      5         // num edge types
#define EMAX     16384
#define ESELMAX  65536

// ---------------- scratch (device globals, no allocs) ----------------
__device__ float g_h   [BNODES*HDIM];
__device__ float g_ht  [BNODES*HDIM];
__device__ float g_Hm  [BNODES*HDIM];
__device__ float g_agg [BNODES*HDIM];
__device__ float g_EAW [EMAX*HDIM];
__device__ float g_embg[BNODES*HDIM];
__device__ float g_A   [BNODES*HDIM];
__device__ float g_B   [BNODES*HDIM];
__device__ float g_WfoldT[5*HDIM];   // [c][k]
__device__ float g_bfold[8];
__device__ float g_propadd[64*HDIM]; // includes b_add
__device__ double g_acc;

// ---------------- setup: folds + property conditioning ----------------
__global__ void setup_kernel(const float* __restrict__ W3, const float* __restrict__ b3,
                             const float* __restrict__ W_out, const float* __restrict__ b_out,
                             const float* __restrict__ props, const float* __restrict__ W_prop,
                             const float* __restrict__ b_prop, const float* __restrict__ W_add,
                             const float* __restrict__ b_add)
{
    int t = threadIdx.x;   // 0..255
    // WfoldT[c][k] = sum_j W3[k][j] * W_out[j][c]
    {
        float s[5] = {0.f,0.f,0.f,0.f,0.f};
        for (int j = 0; j < 512; j++) {
            float w3 = W3[t*512 + j];
            #pragma unroll
            for (int c = 0; c < 5; c++) s[c] += w3 * W_out[j*5 + c];
        }
        #pragma unroll
        for (int c = 0; c < 5; c++) g_WfoldT[c*256 + t] = s[c];
    }
    if (t < 5) {
        float s = b_out[t];
        for (int k = 0; k < 512; k++) s += b3[k] * W_out[k*5 + t];
        g_bfold[t] = s;
    }
    // propadd[b][t] = b_add[t] + sum_p (props[b]*W_prop[p]+b_prop[p]) * W_add[256+p][t]
    for (int b = 0; b < 64; b++) {
        float pv = props[b];
        float s = b_add[t];
        for (int p = 0; p < 64; p++) {
            float pe = pv * W_prop[p] + b_prop[p];
            s += pe * W_add[(256 + p)*256 + t];
        }
        g_propadd[b*256 + t] = s;
    }
    if (t == 0) g_acc = 0.0;
}

// ---------------- EAW[e][n] = b_msg[n] + edge_attr[e] @ W_msg[256:261] ----------------
__global__ void eaw_kernel(const float* __restrict__ ea, const float* __restrict__ W_msg,
                           const float* __restrict__ b_msg)
{
    int e = blockIdx.x;
    int n = threadIdx.x;
    const float* We = W_msg + 256*256;
    float a0 = ea[e*5+0], a1 = ea[e*5+1], a2 = ea[e*5+2], a3 = ea[e*5+3], a4 = ea[e*5+4];
    float s = b_msg[n] + a0*We[n] + a1*We[256+n] + a2*We[512+n] + a3*We[768+n] + a4*We[1024+n];
    g_EAW[e*256 + n] = s;
}

// ---------------- zero ----------------
__global__ void zero_kernel(float* __restrict__ p, int n)
{
    int i = blockIdx.x * blockDim.x + threadIdx.x;
    if (i < n) p[i] = 0.f;
}

// ---------------- generic SGEMM: C[M,256] = act(A1@W1 [+ A2@W2] + bias [+ rowBias]) ----
// M = 4096, N = 256 fixed. BM=128, BN=64, BK=16, 256 threads, 8x4 micro-tile.
__global__ void __launch_bounds__(256)
sgemm256(const float* __restrict__ A1, const float* __restrict__ W1, int K1,
         const float* __restrict__ A2, const float* __restrict__ W2, int K2,
         const float* __restrict__ bias, const float* __restrict__ rowBias,
         float* __restrict__ C, int doRelu)
{
    __shared__ float As[16][132];
    __shared__ float Ws[16][64];
    int tid = threadIdx.x;
    int m0 = blockIdx.y * 128;
    int n0 = blockIdx.x * 64;
    int ty = tid >> 4;     // 0..15 -> 8 rows each
    int tx = tid & 15;     // 0..15 -> 4 cols each
    float acc[8][4];
    #pragma unroll
    for (int i = 0; i < 8; i++)
        #pragma unroll
        for (int j = 0; j < 4; j++) acc[i][j] = 0.f;

    for (int pass = 0; pass < 2; pass++) {
        const float* A = pass ? A2 : A1;
        const float* W = pass ? W2 : W1;
        int K = pass ? K2 : K1;
        if (K == 0) break;
        for (int k0 = 0; k0 < K; k0 += 16) {
            #pragma unroll
            for (int i = 0; i < 2; i++) {
                int f = tid + i*256;            // 0..511 float4s
                int row = f >> 2;               // 0..127
                int kq  = (f & 3) * 4;
                float4 v = *(const float4*)&A[(size_t)(m0 + row)*K + k0 + kq];
                As[kq+0][row] = v.x; As[kq+1][row] = v.y;
                As[kq+2][row] = v.z; As[kq+3][row] = v.w;
            }
            {
                int k  = tid >> 4;
                int nq = (tid & 15) * 4;
                *(float4*)&Ws[k][nq] = *(const float4*)&W[(size_t)(k0 + k)*256 + n0 + nq];
            }
            __syncthreads();
            #pragma unroll
            for (int kk = 0; kk < 16; kk++) {
                float4 a0 = *(const float4*)&As[kk][ty*8];
                float4 a1 = *(const float4*)&As[kk][ty*8 + 4];
                float4 bv = *(const float4*)&Ws[kk][tx*4];
                float a[8] = {a0.x,a0.y,a0.z,a0.w,a1.x,a1.y,a1.z,a1.w};
                float b[4] = {bv.x,bv.y,bv.z,bv.w};
                #pragma unroll
                for (int i = 0; i < 8; i++)
                    #pragma unroll
                    for (int j = 0; j < 4; j++) acc[i][j] += a[i]*b[j];
            }
            __syncthreads();
        }
    }
    // epilogue
    int n = n0 + tx*4;
    float4 bb = make_float4(0.f,0.f,0.f,0.f);
    if (bias) bb = *(const float4*)&bias[n];
    #pragma unroll
    for (int i = 0; i < 8; i++) {
        int m = m0 + ty*8 + i;
        float4 v = make_float4(acc[i][0]+bb.x, acc[i][1]+bb.y, acc[i][2]+bb.z, acc[i][3]+bb.w);
        if (rowBias) {
            const float* rb = rowBias + ((m >> 6) << 8) + n;
            v.x += rb[0]; v.y += rb[1]; v.z += rb[2]; v.w += rb[3];
        }
        if (doRelu) {
            v.x = fmaxf(v.x, 0.f); v.y = fmaxf(v.y, 0.f);
            v.z = fmaxf(v.z, 0.f); v.w = fmaxf(v.w, 0.f);
        }
        *(float4*)&C[(size_t)m*256 + n] = v;
    }
}

// ---------------- edge scatter: agg[dst] += relu(Hm[src] + EAW[e]) ----------------
__global__ void edge_scatter(const int* __restrict__ src, const int* __restrict__ dst,
                             float* __restrict__ agg, int E)
{
    int c = threadIdx.x;
    int base = blockIdx.x * 8;
    #pragma unroll
    for (int q = 0; q < 8; q++) {
        int e = base + q;
        if (e >= E) break;
        int s = src[e], d = dst[e];
        float v = fmaxf(g_Hm[(size_t)s*256 + c] + g_EAW[(size_t)e*256 + c], 0.f);
        atomicAdd(&agg[(size_t)d*256 + c], v);
    }
}

// ---------------- pair megakernel: h1 gather -> h2 GEMM -> logits -> loss ----------
// 64 pair-rows per block, 256 threads, fused epilogue with folded [256,5] output.
__global__ void __launch_bounds__(256, 2)
pair_kernel(const float* __restrict__ Ag, const float* __restrict__ Bg,
            const int* __restrict__ sel_b, const int* __restrict__ sel_i,
            const int* __restrict__ sel_j, const int* __restrict__ golden,
            const float* __restrict__ W2, const float* __restrict__ b2)
{
    extern __shared__ float smem[];
    float* h1s = smem;                  // [64][260] reused for h2
    float* w2s = h1s + 64*260;          // [16][256]
    float* wfs = w2s + 16*256;          // [5][256]
    float* b2s = wfs + 5*256;           // [256]
    float* bfs = b2s + 256;             // [8]

    int tid  = threadIdx.x;
    int ty   = tid >> 5;                // warp id 0..7
    int lane = tid & 31;
    int tx   = lane;                    // col group 0..31
    int e0   = blockIdx.x * 64;

    // param loads
    for (int i = tid; i < 5*256; i += 256) wfs[i] = g_WfoldT[i];
    b2s[tid] = b2[tid];
    if (tid < 5) bfs[tid] = g_bfold[tid];

    // gather phase: h1 = relu(A[bi*64+si] + B[bi*64+sj])
    #pragma unroll
    for (int t = 0; t < 8; t++) {
        int r = ty*8 + t;
        int e = e0 + r;
        int bsel = sel_b[e];
        int ii = bsel*64 + sel_i[e];
        int jj = bsel*64 + sel_j[e];
        const float* ap = Ag + (size_t)ii*256;
        const float* bp = Bg + (size_t)jj*256;
        #pragma unroll
        for (int q = 0; q < 2; q++) {
            int c = lane*4 + q*128;
            float4 av = *(const float4*)(ap + c);
            float4 bv = *(const float4*)(bp + c);
            float4 hv = make_float4(fmaxf(av.x+bv.x,0.f), fmaxf(av.y+bv.y,0.f),
                                    fmaxf(av.z+bv.z,0.f), fmaxf(av.w+bv.w,0.f));
            *(float4*)&h1s[r*260 + c] = hv;
        }
    }
    __syncthreads();

    // GEMM: h2[64,256] = h1[64,256] @ W2[256,256]
    float acc[8][8];
    #pragma unroll
    for (int i = 0; i < 8; i++)
        #pragma unroll
        for (int j = 0; j < 8; j++) acc[i][j] = 0.f;

    for (int kt = 0; kt < 16; kt++) {
        #pragma unroll
        for (int i = 0; i < 4; i++) {
            int f  = tid + i*256;        // 0..1023 float4s
            int k  = f >> 6;             // 0..15
            int cq = (f & 63) * 4;
            *(float4*)&w2s[k*256 + cq] = *(const float4*)&W2[(size_t)(kt*16 + k)*256 + cq];
        }
        __syncthreads();
        #pragma unroll
        for (int kk = 0; kk < 16; kk++) {
            float a[8];
            #pragma unroll
            for (int i = 0; i < 8; i++) a[i] = h1s[(ty*8 + i)*260 + kt*16 + kk];
            float4 b0 = *(const float4*)&w2s[kk*256 + tx*4];
            float4 b1 = *(const float4*)&w2s[kk*256 + 128 + tx*4];
            #pragma unroll
            for (int i = 0; i < 8; i++) {
                acc[i][0] += a[i]*b0.x; acc[i][1] += a[i]*b0.y;
                acc[i][2] += a[i]*b0.z; acc[i][3] += a[i]*b0.w;
                acc[i][4] += a[i]*b1.x; acc[i][5] += a[i]*b1.y;
                acc[i][6] += a[i]*b1.z; acc[i][7] += a[i]*b1.w;
            }
        }
        __syncthreads();
    }

    // write h2 = relu(acc + b2) over h1 buffer
    #pragma unroll
    for (int i = 0; i < 8; i++) {
        int r = ty*8 + i;
        float4 v = make_float4(fmaxf(acc[i][0]+b2s[tx*4+0],0.f), fmaxf(acc[i][1]+b2s[tx*4+1],0.f),
                               fmaxf(acc[i][2]+b2s[tx*4+2],0.f), fmaxf(acc[i][3]+b2s[tx*4+3],0.f));
        *(float4*)&h1s[r*260 + tx*4] = v;
        float4 u = make_float4(fmaxf(acc[i][4]+b2s[128+tx*4+0],0.f), fmaxf(acc[i][5]+b2s[128+tx*4+1],0.f),
                               fmaxf(acc[i][6]+b2s[128+tx*4+2],0.f), fmaxf(acc[i][7]+b2s[128+tx*4+3],0.f));
        *(float4*)&h1s[r*260 + 128 + tx*4] = u;
    }
    __syncthreads();

    // logits = h2 @ WfoldT^T + bfold ; loss = lse - logit[gold]
    double lsum = 0.0;
    for (int t = 0; t < 8; t++) {
        int r = ty*8 + t;
        float p[5] = {0.f,0.f,0.f,0.f,0.f};
        #pragma unroll
        for (int m = 0; m < 8; m++) {
            int k = lane + 32*m;
            float hv = h1s[r*260 + k];
            #pragma unroll
            for (int c = 0; c < 5; c++) p[c] += hv * wfs[c*256 + k];
        }
        #pragma unroll
        for (int off = 16; off; off >>= 1)
            #pragma unroll
            for (int c = 0; c < 5; c++) p[c] += __shfl_xor_sync(0xffffffffu, p[c], off);
        if (lane == 0) {
            float lg[5], mx = -1e30f;
            #pragma unroll
            for (int c = 0; c < 5; c++) { lg[c] = p[c] + bfs[c]; mx = fmaxf(mx, lg[c]); }
            float s = 0.f;
            #pragma unroll
            for (int c = 0; c < 5; c++) s += expf(lg[c] - mx);
            float lse = mx + logf(s);
            int gold = golden[e0 + r];
            lsum += (double)(lse - lg[gold]);
        }
    }
    if (lane == 0) atomicAdd(&g_acc, lsum);
}

// ---------------- finalize ----------------
__global__ void finalize_kernel(float* __restrict__ out, int esel)
{
    out[0] = (float)(g_acc / (double)esel);
}

// ---------------- host launcher ----------------
extern "C" void kernel_launch(void* const* d_in, const int* in_sizes, int n_in,
                              void* d_out, int out_size)
{
    const float* x         = (const float*)d_in[0];
    const int*   eidx      = (const int*)  d_in[1];
    const float* edge_attr = (const float*)d_in[2];
    const float* props     = (const float*)d_in[3];
    const int*   sel_b     = (const int*)  d_in[4];
    const int*   sel_i     = (const int*)  d_in[5];
    const int*   sel_j     = (const int*)  d_in[6];
    const int*   golden    = (const int*)  d_in[7];
    const float* W_prop = (const float*)d_in[8];
    const float* b_prop = (const float*)d_in[9];
    const float* W_in   = (const float*)d_in[10];
    const float* b_in   = (const float*)d_in[11];
    const float* W_msg  = (const float*)d_in[12];
    const float* b_msg  = (const float*)d_in[13];
    const float* W_upd  = (const float*)d_in[14];
    const float* b_upd  = (const float*)d_in[15];
    const float* W_add  = (const float*)d_in[16];
    const float* b_add  = (const float*)d_in[17];
    const float* W1     = (const float*)d_in[18];
    const float* b1     = (const float*)d_in[19];
    const float* W2     = (const float*)d_in[20];
    const float* b2     = (const float*)d_in[21];
    const float* W3     = (const float*)d_in[22];
    const float* b3     = (const float*)d_in[23];
    const float* W_out  = (const float*)d_in[24];
    const float* b_out  = (const float*)d_in[25];

    int E    = in_sizes[1] / 2;
    int ESEL = in_sizes[4];
    const int* src = eidx;
    const int* dst = eidx + E;

    float *p_h, *p_ht, *p_agg, *p_embg, *p_A, *p_B;
    cudaGetSymbolAddress((void**)&p_h,    g_h);
    cudaGetSymbolAddress((void**)&p_ht,   g_ht);
    cudaGetSymbolAddress((void**)&p_agg,  g_agg);
    cudaGetSymbolAddress((void**)&p_embg, g_embg);
    cudaGetSymbolAddress((void**)&p_A,    g_A);
    cudaGetSymbolAddress((void**)&p_B,    g_B);
    float* p_Hm; cudaGetSymbolAddress((void**)&p_Hm, g_Hm);

    int pairSmem = (64*260 + 16*256 + 5*256 + 256 + 8) * (int)sizeof(float);
    cudaFuncSetAttribute(pair_kernel, cudaFuncAttributeMaxDynamicSharedMemorySize, pairSmem);

    dim3 gemmGrid(4, BNODES/128);   // N=256/64, M=4096/128

    // setup + loop-invariant edge transform
    setup_kernel<<<1, 256>>>(W3, b3, W_out, b_out, props, W_prop, b_prop, W_add, b_add);
    eaw_kernel<<<E, 256>>>(edge_attr, W_msg, b_msg);

    // h0 = relu(x @ W_in + b_in)
    sgemm256<<<gemmGrid, 256>>>(x, W_in, 192, nullptr, nullptr, 0, b_in, nullptr, p_h, 1);

    float* cur = p_h;
    float* nxt = p_ht;
    for (int t = 0; t < 4; t++) {
        zero_kernel<<<(BNODES*HDIM + 255)/256, 256>>>(p_agg, BNODES*HDIM);
        // Hm = h @ W_msg[0:256]
        sgemm256<<<gemmGrid, 256>>>(cur, W_msg, 256, nullptr, nullptr, 0, nullptr, nullptr, p_Hm, 0);
        // agg[dst] += relu(Hm[src] + EAW)
        edge_scatter<<<(E + 7)/8, 256>>>(src, dst, p_agg, E);
        // h = relu(h@W_upd_top + agg@W_upd_bot + b_upd)
        sgemm256<<<gemmGrid, 256>>>(cur, W_upd, 256, p_agg, W_upd + 256*256, 256,
                                    b_upd, nullptr, nxt, 1);
        float* tmp = cur; cur = nxt; nxt = tmp;
    }

    // embg = h @ W_add[0:256] + propadd[b]   (no relu)
    float* p_propadd; cudaGetSymbolAddress((void**)&p_propadd, g_propadd);
    sgemm256<<<gemmGrid, 256>>>(cur, W_add, 256, nullptr, nullptr, 0, nullptr, p_propadd, p_embg, 0);

    // A = embg @ W1[0:256] + b1 ; B = embg @ W1[256:512]
    sgemm256<<<gemmGrid, 256>>>(p_embg, W1, 256, nullptr, nullptr, 0, b1, nullptr, p_A, 0);
    sgemm256<<<gemmGrid, 256>>>(p_embg, W1 + 256*256, 256, nullptr, nullptr, 0, nullptr, nullptr, p_B, 0);

    // pair stage + loss
    pair_kernel<<<ESEL/64, 256, pairSmem>>>(p_A, p_B, sel_b, sel_i, sel_j, golden, W2, b2);

    finalize_kernel<<<1, 1>>>((float*)d_out, ESEL);
}

// round 2
// speedup vs baseline: 1.5354x; 1.5354x over previous
#include <cuda_runtime.h>
#include <math.h>
#include <stdint.h>

// ---------------- problem constants ----------------
#define BNODES   4096      // B*N
#define HDIM     256
#define EMAX     16384

// ---------------- scratch (device globals, no allocs) ----------------
__device__ float g_h   [BNODES*HDIM];
__device__ float g_ht  [BNODES*HDIM];
__device__ float g_Hm  [BNODES*HDIM];
__device__ float g_agg [BNODES*HDIM];
__device__ float g_EAW [EMAX*HDIM];
__device__ float g_embg[BNODES*HDIM];
__device__ float g_A   [BNODES*HDIM];
__device__ float g_B   [BNODES*HDIM];
__device__ float g_WfoldT[5*HDIM];   // [c][k]
__device__ float g_bfold[8];
__device__ float g_propadd[64*HDIM]; // includes b_add
__device__ double g_acc;

// ---------------- helpers ----------------
__device__ __forceinline__ uint32_t f2tf32(float x) {
    uint32_t r;
    asm("cvt.rna.tf32.f32 %0, %1;" : "=r"(r) : "f"(x));
    return r;
}

__device__ __forceinline__ void mma_tf32(float& d0, float& d1, float& d2, float& d3,
                                         uint32_t a0, uint32_t a1, uint32_t a2, uint32_t a3,
                                         uint32_t b0, uint32_t b1)
{
    asm volatile(
        "mma.sync.aligned.m16n8k8.row.col.f32.tf32.tf32.f32 "
        "{%0,%1,%2,%3}, {%4,%5,%6,%7}, {%8,%9}, {%0,%1,%2,%3};"
        : "+f"(d0), "+f"(d1), "+f"(d2), "+f"(d3)
        : "r"(a0), "r"(a1), "r"(a2), "r"(a3), "r"(b0), "r"(b1));
}

// ---------------- setup: folds + property conditioning ----------------
__global__ void setup_kernel(const float* __restrict__ W3, const float* __restrict__ b3,
                             const float* __restrict__ W_out, const float* __restrict__ b_out,
                             const float* __restrict__ props, const float* __restrict__ W_prop,
                             const float* __restrict__ b_prop, const float* __restrict__ W_add,
                             const float* __restrict__ b_add)
{
    int t = threadIdx.x;   // 0..255
    {
        float s[5] = {0.f,0.f,0.f,0.f,0.f};
        for (int j = 0; j < 512; j++) {
            float w3 = W3[t*512 + j];
            #pragma unroll
            for (int c = 0; c < 5; c++) s[c] += w3 * W_out[j*5 + c];
        }
        #pragma unroll
        for (int c = 0; c < 5; c++) g_WfoldT[c*256 + t] = s[c];
    }
    if (t < 5) {
        float s = b_out[t];
        for (int k = 0; k < 512; k++) s += b3[k] * W_out[k*5 + t];
        g_bfold[t] = s;
    }
    for (int b = 0; b < 64; b++) {
        float pv = props[b];
        float s = b_add[t];
        for (int p = 0; p < 64; p++) {
            float pe = pv * W_prop[p] + b_prop[p];
            s += pe * W_add[(256 + p)*256 + t];
        }
        g_propadd[b*256 + t] = s;
    }
    if (t == 0) g_acc = 0.0;
}

// ---------------- EAW[e][n] = b_msg[n] + edge_attr[e] @ W_msg[256:261] ----------------
__global__ void eaw_kernel(const float* __restrict__ ea, const float* __restrict__ W_msg,
                           const float* __restrict__ b_msg)
{
    int e = blockIdx.x;
    int n = threadIdx.x;
    const float* We = W_msg + 256*256;
    float a0 = ea[e*5+0], a1 = ea[e*5+1], a2 = ea[e*5+2], a3 = ea[e*5+3], a4 = ea[e*5+4];
    float s = b_msg[n] + a0*We[n] + a1*We[256+n] + a2*We[512+n] + a3*We[768+n] + a4*We[1024+n];
    g_EAW[e*256 + n] = s;
}

// ---------------- tf32 tensor-core SGEMM ----------------
// C[4096,256] = act(A1@W1 [+ A2@W2] + bias [+ rowBias])
// BM=64, BN=128, BK=32, 128 threads (4 warps, 2m x 2n), warp tile 32x64.
__global__ void __launch_bounds__(128)
sgemm_tc(const float* __restrict__ A1, const float* __restrict__ W1, int K1,
         const float* __restrict__ A2, const float* __restrict__ W2, int K2,
         const float* __restrict__ bias, const float* __restrict__ rowBias,
         float* __restrict__ C, int doRelu)
{
    __shared__ uint32_t As[32][68];    // [k][m], tf32
    __shared__ uint32_t Ws[32][132];   // [k][n], tf32

    int tid = threadIdx.x;
    int wid = tid >> 5;
    int lane = tid & 31;
    int warp_m = wid & 1;              // 0..1
    int warp_n = wid >> 1;             // 0..1
    int gi = lane >> 2;                // groupID 0..7
    int tg = lane & 3;                 // thread-in-group 0..3

    int m0 = blockIdx.y * 64;
    int n0 = blockIdx.x * 128;

    float acc[2][8][4];
    #pragma unroll
    for (int mt = 0; mt < 2; mt++)
        #pragma unroll
        for (int nt = 0; nt < 8; nt++)
            #pragma unroll
            for (int q = 0; q < 4; q++) acc[mt][nt][q] = 0.f;

    for (int pass = 0; pass < 2; pass++) {
        const float* A = pass ? A2 : A1;
        const float* W = pass ? W2 : W1;
        int K = pass ? K2 : K1;
        if (K == 0) break;
        for (int k0 = 0; k0 < K; k0 += 32) {
            // load A tile [64 rows x 32 k], transpose -> As[k][m]
            #pragma unroll
            for (int i = 0; i < 4; i++) {
                int f = tid + i*128;           // 0..511 float4s
                int row = f >> 3;              // 0..63
                int kq  = (f & 7) * 4;
                float4 v = *(const float4*)&A[(size_t)(m0 + row)*K + k0 + kq];
                As[kq+0][row] = f2tf32(v.x); As[kq+1][row] = f2tf32(v.y);
                As[kq+2][row] = f2tf32(v.z); As[kq+3][row] = f2tf32(v.w);
            }
            // load W tile [32 k x 128 n]
            #pragma unroll
            for (int i = 0; i < 8; i++) {
                int f  = tid + i*128;          // 0..1023 float4s
                int k  = f >> 5;               // 0..31
                int nq = (f & 31) * 4;
                float4 v = *(const float4*)&W[(size_t)(k0 + k)*256 + n0 + nq];
                Ws[k][nq+0] = f2tf32(v.x); Ws[k][nq+1] = f2tf32(v.y);
                Ws[k][nq+2] = f2tf32(v.z); Ws[k][nq+3] = f2tf32(v.w);
            }
            __syncthreads();
            #pragma unroll
            for (int ks = 0; ks < 4; ks++) {
                int kb = ks*8;
                uint32_t a[2][4];
                #pragma unroll
                for (int mt = 0; mt < 2; mt++) {
                    int m = warp_m*32 + mt*16 + gi;
                    a[mt][0] = As[kb + tg    ][m];
                    a[mt][1] = As[kb + tg    ][m + 8];
                    a[mt][2] = As[kb + tg + 4][m];
                    a[mt][3] = As[kb + tg + 4][m + 8];
                }
                #pragma unroll
                for (int nt = 0; nt < 8; nt++) {
                    int n = warp_n*64 + nt*8 + gi;
                    uint32_t b0 = Ws[kb + tg    ][n];
                    uint32_t b1 = Ws[kb + tg + 4][n];
                    #pragma unroll
                    for (int mt = 0; mt < 2; mt++)
                        mma_tf32(acc[mt][nt][0], acc[mt][nt][1], acc[mt][nt][2], acc[mt][nt][3],
                                 a[mt][0], a[mt][1], a[mt][2], a[mt][3], b0, b1);
                }
            }
            __syncthreads();
        }
    }

    // epilogue
    #pragma unroll
    for (int mt = 0; mt < 2; mt++) {
        #pragma unroll
        for (int half = 0; half < 2; half++) {
            int m = m0 + warp_m*32 + mt*16 + gi + half*8;
            #pragma unroll
            for (int nt = 0; nt < 8; nt++) {
                int n = n0 + warp_n*64 + nt*8 + tg*2;
                float v0 = acc[mt][nt][half*2 + 0];
                float v1 = acc[mt][nt][half*2 + 1];
                if (bias)    { v0 += bias[n];   v1 += bias[n+1]; }
                if (rowBias) {
                    const float* rb = rowBias + ((m >> 6) << 8);
                    v0 += rb[n]; v1 += rb[n+1];
                }
                if (doRelu)  { v0 = fmaxf(v0, 0.f); v1 = fmaxf(v1, 0.f); }
                float2 o = make_float2(v0, v1);
                *(float2*)&C[(size_t)m*256 + n] = o;
            }
        }
    }
}

// ---------------- edge scatter: agg[dst] += relu(Hm[src] + EAW[e]) ----------------
__global__ void edge_scatter(const int* __restrict__ src, const int* __restrict__ dst,
                             float* __restrict__ agg, int E)
{
    int c = threadIdx.x;
    int base = blockIdx.x * 8;
    #pragma unroll
    for (int q = 0; q < 8; q++) {
        int e = base + q;
        if (e >= E) break;
        int s = src[e], d = dst[e];
        float v = fmaxf(g_Hm[(size_t)s*256 + c] + g_EAW[(size_t)e*256 + c], 0.f);
        atomicAdd(&agg[(size_t)d*256 + c], v);
    }
}

// ---------------- pair megakernel (tensor-core h2 GEMM) ----------------
// 64 pair-rows per block, 256 threads (8 warps, 2m x 4n), warp tile 32x64.
__global__ void __launch_bounds__(256, 2)
pair_kernel(const float* __restrict__ Ag, const float* __restrict__ Bg,
            const int* __restrict__ sel_b, const int* __restrict__ sel_i,
            const int* __restrict__ sel_j, const int* __restrict__ golden,
            const float* __restrict__ W2, const float* __restrict__ b2)
{
    extern __shared__ uint32_t smem[];
    uint32_t* h1u = smem;                   // [64][260] tf32, reused as fp32 h2
    uint32_t* w2u = h1u + 64*260;           // [32][260] tf32
    float*    wfs = (float*)(w2u + 32*260); // [5][256]
    float*    b2s = wfs + 5*256;            // [256]
    float*    bfs = b2s + 256;              // [8]
    float*    h1f = (float*)h1u;

    int tid  = threadIdx.x;
    int wid  = tid >> 5;
    int lane = tid & 31;
    int warp_m = wid & 1;                  // 0..1
    int warp_n = wid >> 1;                 // 0..3
    int gi = lane >> 2;
    int tg = lane & 3;
    int e0 = blockIdx.x * 64;

    // param loads
    for (int i = tid; i < 5*256; i += 256) wfs[i] = g_WfoldT[i];
    b2s[tid] = b2[tid];
    if (tid < 5) bfs[tid] = g_bfold[tid];

    // gather phase: h1 = relu(A[bi*64+si] + B[bi*64+sj]), stored tf32 [row][260]
    #pragma unroll
    for (int t = 0; t < 8; t++) {
        int r = wid*8 + t;
        int e = e0 + r;
        int bsel = sel_b[e];
        int ii = bsel*64 + sel_i[e];
        int jj = bsel*64 + sel_j[e];
        const float* ap = Ag + (size_t)ii*256;
        const float* bp = Bg + (size_t)jj*256;
        #pragma unroll
        for (int q = 0; q < 2; q++) {
            int c = lane*4 + q*128;
            float4 av = *(const float4*)(ap + c);
            float4 bv = *(const float4*)(bp + c);
            h1u[r*260 + c + 0] = f2tf32(fmaxf(av.x + bv.x, 0.f));
            h1u[r*260 + c + 1] = f2tf32(fmaxf(av.y + bv.y, 0.f));
            h1u[r*260 + c + 2] = f2tf32(fmaxf(av.z + bv.z, 0.f));
            h1u[r*260 + c + 3] = f2tf32(fmaxf(av.w + bv.w, 0.f));
        }
    }
    __syncthreads();

    // GEMM: h2[64,256] = h1[64,256] @ W2[256,256], tf32 MMA
    float acc[2][8][4];
    #pragma unroll
    for (int mt = 0; mt < 2; mt++)
        #pragma unroll
        for (int nt = 0; nt < 8; nt++)
            #pragma unroll
            for (int q = 0; q < 4; q++) acc[mt][nt][q] = 0.f;

    for (int k0 = 0; k0 < 256; k0 += 32) {
        // load W2 k-block [32][256]
        #pragma unroll
        for (int i = 0; i < 8; i++) {
            int f  = tid + i*256;             // 0..2047 float4s
            int k  = f >> 6;                  // 0..31
            int nq = (f & 63) * 4;
            float4 v = *(const float4*)&W2[(size_t)(k0 + k)*256 + nq];
            w2u[k*260 + nq + 0] = f2tf32(v.x); w2u[k*260 + nq + 1] = f2tf32(v.y);
            w2u[k*260 + nq + 2] = f2tf32(v.z); w2u[k*260 + nq + 3] = f2tf32(v.w);
        }
        __syncthreads();
        #pragma unroll
        for (int ks = 0; ks < 4; ks++) {
            int kb = ks*8;
            uint32_t a[2][4];
            #pragma unroll
            for (int mt = 0; mt < 2; mt++) {
                int m = warp_m*32 + mt*16 + gi;
                a[mt][0] = h1u[(m    )*260 + k0 + kb + tg    ];
                a[mt][1] = h1u[(m + 8)*260 + k0 + kb + tg    ];
                a[mt][2] = h1u[(m    )*260 + k0 + kb + tg + 4];
                a[mt][3] = h1u[(m + 8)*260 + k0 + kb + tg + 4];
            }
            #pragma unroll
            for (int nt = 0; nt < 8; nt++) {
                int n = warp_n*64 + nt*8 + gi;
                uint32_t b0 = w2u[(kb + tg    )*260 + n];
                uint32_t b1 = w2u[(kb + tg + 4)*260 + n];
                #pragma unroll
                for (int mt = 0; mt < 2; mt++)
                    mma_tf32(acc[mt][nt][0], acc[mt][nt][1], acc[mt][nt][2], acc[mt][nt][3],
                             a[mt][0], a[mt][1], a[mt][2], a[mt][3], b0, b1);
            }
        }
        __syncthreads();
    }

    // h2 = relu(acc + b2), written as fp32 over the h1 buffer
    #pragma unroll
    for (int mt = 0; mt < 2; mt++) {
        #pragma unroll
        for (int half = 0; half < 2; half++) {
            int m = warp_m*32 + mt*16 + gi + half*8;
            #pragma unroll
            for (int nt = 0; nt < 8; nt++) {
                int n = warp_n*64 + nt*8 + tg*2;
                float v0 = fmaxf(acc[mt][nt][half*2 + 0] + b2s[n],     0.f);
                float v1 = fmaxf(acc[mt][nt][half*2 + 1] + b2s[n + 1], 0.f);
                h1f[m*260 + n]     = v0;
                h1f[m*260 + n + 1] = v1;
            }
        }
    }
    __syncthreads();

    // logits = h2 @ WfoldT^T + bfold ; loss = lse - logit[gold]
    double lsum = 0.0;
    for (int t = 0; t < 8; t++) {
        int r = wid*8 + t;
        float p[5] = {0.f,0.f,0.f,0.f,0.f};
        #pragma unroll
        for (int m8 = 0; m8 < 8; m8++) {
            int k = lane + 32*m8;
            float hv = h1f[r*260 + k];
            #pragma unroll
            for (int c = 0; c < 5; c++) p[c] += hv * wfs[c*256 + k];
        }
        #pragma unroll
        for (int off = 16; off; off >>= 1)
            #pragma unroll
            for (int c = 0; c < 5; c++) p[c] += __shfl_xor_sync(0xffffffffu, p[c], off);
        if (lane == 0) {
            float lg[5], mx = -1e30f;
            #pragma unroll
            for (int c = 0; c < 5; c++) { lg[c] = p[c] + bfs[c]; mx = fmaxf(mx, lg[c]); }
            float s = 0.f;
            #pragma unroll
            for (int c = 0; c < 5; c++) s += expf(lg[c] - mx);
            float lse = mx + logf(s);
            int gold = golden[e0 + r];
            lsum += (double)(lse - lg[gold]);
        }
    }
    if (lane == 0) atomicAdd(&g_acc, lsum);
}

// ---------------- finalize ----------------
__global__ void finalize_kernel(float* __restrict__ out, int esel)
{
    out[0] = (float)(g_acc / (double)esel);
}

// ---------------- host launcher ----------------
extern "C" void kernel_launch(void* const* d_in, const int* in_sizes, int n_in,
                              void* d_out, int out_size)
{
    const float* x         = (const float*)d_in[0];
    const int*   eidx      = (const int*)  d_in[1];
    const float* edge_attr = (const float*)d_in[2];
    const float* props     = (const float*)d_in[3];
    const int*   sel_b     = (const int*)  d_in[4];
    const int*   sel_i     = (const int*)  d_in[5];
    const int*   sel_j     = (const int*)  d_in[6];
    const int*   golden    = (const int*)  d_in[7];
    const float* W_prop = (const float*)d_in[8];
    const float* b_prop = (const float*)d_in[9];
    const float* W_in   = (const float*)d_in[10];
    const float* b_in   = (const float*)d_in[11];
    const float* W_msg  = (const float*)d_in[12];
    const float* b_msg  = (const float*)d_in[13];
    const float* W_upd  = (const float*)d_in[14];
    const float* b_upd  = (const float*)d_in[15];
    const float* W_add  = (const float*)d_in[16];
    const float* b_add  = (const float*)d_in[17];
    const float* W1     = (const float*)d_in[18];
    const float* b1     = (const float*)d_in[19];
    const float* W2     = (const float*)d_in[20];
    const float* b2     = (const float*)d_in[21];
    const float* W3     = (const float*)d_in[22];
    const float* b3     = (const float*)d_in[23];
    const float* W_out  = (const float*)d_in[24];
    const float* b_out  = (const float*)d_in[25];

    int E    = in_sizes[1] / 2;
    int ESEL = in_sizes[4];
    const int* src = eidx;
    const int* dst = eidx + E;

    float *p_h, *p_ht, *p_agg, *p_embg, *p_A, *p_B, *p_Hm, *p_propadd;
    cudaGetSymbolAddress((void**)&p_h,    g_h);
    cudaGetSymbolAddress((void**)&p_ht,   g_ht);
    cudaGetSymbolAddress((void**)&p_agg,  g_agg);
    cudaGetSymbolAddress((void**)&p_embg, g_embg);
    cudaGetSymbolAddress((void**)&p_A,    g_A);
    cudaGetSymbolAddress((void**)&p_B,    g_B);
    cudaGetSymbolAddress((void**)&p_Hm,   g_Hm);
    cudaGetSymbolAddress((void**)&p_propadd, g_propadd);

    int pairSmem = (64*260 + 32*260 + 5*256 + 256 + 8) * (int)sizeof(float);
    cudaFuncSetAttribute(pair_kernel, cudaFuncAttributeMaxDynamicSharedMemorySize, pairSmem);

    dim3 gemmGrid(2, BNODES/64);   // N=256/128, M=4096/64

    setup_kernel<<<1, 256>>>(W3, b3, W_out, b_out, props, W_prop, b_prop, W_add, b_add);
    eaw_kernel<<<E, 256>>>(edge_attr, W_msg, b_msg);

    // h0 = relu(x @ W_in + b_in)
    sgemm_tc<<<gemmGrid, 128>>>(x, W_in, 192, nullptr, nullptr, 0, b_in, nullptr, p_h, 1);

    float* cur = p_h;
    float* nxt = p_ht;
    for (int t = 0; t < 4; t++) {
        cudaMemsetAsync(p_agg, 0, (size_t)BNODES*HDIM*sizeof(float));
        // Hm = h @ W_msg[0:256]
        sgemm_tc<<<gemmGrid, 128>>>(cur, W_msg, 256, nullptr, nullptr, 0, nullptr, nullptr, p_Hm, 0);
        // agg[dst] += relu(Hm[src] + EAW)
        edge_scatter<<<(E + 7)/8, 256>>>(src, dst, p_agg, E);
        // h = relu(h@W_upd_top + agg@W_upd_bot + b_upd)
        sgemm_tc<<<gemmGrid, 128>>>(cur, W_upd, 256, p_agg, W_upd + 256*256, 256,
                                    b_upd, nullptr, nxt, 1);
        float* tmp = cur; cur = nxt; nxt = tmp;
    }

    // embg = h @ W_add[0:256] + propadd[b]   (no relu)
    sgemm_tc<<<gemmGrid, 128>>>(cur, W_add, 256, nullptr, nullptr, 0, nullptr, p_propadd, p_embg, 0);

    // A = embg @ W1[0:256] + b1 ; B = embg @ W1[256:512]
    sgemm_tc<<<gemmGrid, 128>>>(p_embg, W1, 256, nullptr, nullptr, 0, b1, nullptr, p_A, 0);
    sgemm_tc<<<gemmGrid, 128>>>(p_embg, W1 + 256*256, 256, nullptr, nullptr, 0, nullptr, nullptr, p_B, 0);

    // pair stage + loss
    pair_kernel<<<ESEL/64, 256, pairSmem>>>(p_A, p_B, sel_b, sel_i, sel_j, golden, W2, b2);

    finalize_kernel<<<1, 1>>>((float*)d_out, ESEL);
}